// round 1
// baseline (speedup 1.0000x reference)
#include <cuda_runtime.h>
#include <cuda_fp16.h>

typedef unsigned long long ull;

#define SQRTD_F  ((float)11.313708498984761)
#define TOK_PER_BLK 64
#define NTHREADS 256

// shared memory byte offsets
#define PIT_OFF  0                         // PiT padded [128][132] f32 : 67584 B
#define PIS_OFF  67584                     // Pi  padded [128][132] f32 : 67584 B
#define XD_OFF   135168                    // X dup pairs [64][128] f32x2 : 65536 B
#define PART_OFF 200704                    // 256 f32
#define CN_OFF   201728                    // 64 f32 clipped norms
#define NH_OFF   201984                    // 64 f32 fp16-roundtripped norms
#define MID_OFF  202240                    // 15 f32 midpoints
#define CSD_OFF  202304                    // 16 f32 codebook/sqrt_d
#define SMEM_BYTES 202368

__device__ __forceinline__ unsigned smem_u32(const void* p) {
    unsigned r;
    asm("{ .reg .u64 t; cvta.to.shared.u64 t, %1; cvt.u32.u64 %0, t; }" : "=r"(r) : "l"(p));
    return r;
}
__device__ __forceinline__ void lds_v2u64(ull& a, ull& b, unsigned addr) {
    asm volatile("ld.shared.v2.u64 {%0,%1}, [%2];" : "=l"(a), "=l"(b) : "r"(addr));
}
__device__ __forceinline__ void fma2(ull& d, ull a, ull b) {
    asm("fma.rn.f32x2 %0, %1, %2, %0;" : "+l"(d) : "l"(a), "l"(b));
}
__device__ __forceinline__ float2 u2f(ull u) {
    float2 f; asm("mov.b64 {%0,%1}, %2;" : "=f"(f.x), "=f"(f.y) : "l"(u)); return f;
}

__global__ __launch_bounds__(NTHREADS, 1)
void turboquant_kernel(const float* __restrict__ x,
                       const float* __restrict__ Pi,
                       const float* __restrict__ cb,
                       float* __restrict__ out,
                       int ntok) {
    extern __shared__ char sm[];
    float* s_pit  = (float*)(sm + PIT_OFF);
    float* s_pis  = (float*)(sm + PIS_OFF);
    float* s_part = (float*)(sm + PART_OFF);
    float* s_cn   = (float*)(sm + CN_OFF);
    float* s_nh   = (float*)(sm + NH_OFF);
    float* s_mid  = (float*)(sm + MID_OFF);
    float* s_csd  = (float*)(sm + CSD_OFF);

    const int tid = threadIdx.x;
    const int tok0 = blockIdx.x * TOK_PER_BLK;

    // ---- Phase 1: stage Pi (row-major, padded) and PiT (transposed, padded) ----
    {
        const float4* Pi4 = (const float4*)Pi;
        #pragma unroll
        for (int e4 = tid; e4 < 4096; e4 += NTHREADS) {
            float4 p = Pi4[e4];
            int e = e4 * 4;
            int j = e >> 7;           // row of Pi
            int i = e & 127;          // col of Pi
            *(float4*)(s_pis + j * 132 + i) = p;   // Pi row-major
            s_pit[(i + 0) * 132 + j] = p.x;        // transposed
            s_pit[(i + 1) * 132 + j] = p.y;
            s_pit[(i + 2) * 132 + j] = p.z;
            s_pit[(i + 3) * 132 + j] = p.w;
        }
    }

    // ---- Phase 2: load x tile into registers, partial sum-of-squares ----
    const int token   = tid >> 2;      // 0..63
    const int quarter = tid & 3;       // 0..3
    float v[32];
    float ss = 0.f;
    {
        const float4* xr = (const float4*)(x + (size_t)(tok0 + token) * 128 + quarter * 32);
        #pragma unroll
        for (int f = 0; f < 8; f++) {
            float4 t = xr[f];
            v[f * 4 + 0] = t.x; v[f * 4 + 1] = t.y; v[f * 4 + 2] = t.z; v[f * 4 + 3] = t.w;
            ss += t.x * t.x; ss += t.y * t.y; ss += t.z * t.z; ss += t.w * t.w;
        }
    }
    s_part[tid] = ss;

    // codebook-derived tables
    if (tid < 16) {
        float c = cb[tid];
        s_csd[tid] = __fdiv_rn(c, SQRTD_F);        // codebook[idx]/sqrt_d (fp32 IEEE div)
        if (tid < 15) s_mid[tid] = (c + cb[tid + 1]) * 0.5f;
    }
    __syncthreads();

    // ---- Phase 3: norms (64 tokens) ----
    if (tid < 64) {
        float s = s_part[4 * tid] + s_part[4 * tid + 1] + s_part[4 * tid + 2] + s_part[4 * tid + 3];
        float n = __fsqrt_rn(s);
        s_cn[tid] = fmaxf(n, 1e-8f);
        s_nh[tid] = __half2float(__float2half_rn(n));
    }
    __syncthreads();

    // ---- Phase 4: write x_unit as duplicated float2 pairs into Xd ----
    {
        float c = s_cn[token];
        float4* xd4 = (float4*)(sm + XD_OFF + (size_t)(token * 128 + quarter * 32) * 8);
        #pragma unroll
        for (int e = 0; e < 16; e++) {
            float u0 = __fdiv_rn(v[2 * e + 0], c);
            float u1 = __fdiv_rn(v[2 * e + 1], c);
            xd4[e] = make_float4(u0, u0, u1, u1);
        }
    }
    __syncthreads();

    // ---- GEMM thread mapping: tn covers N in groups of 8, tmg covers M in groups of 4 ----
    const int tn  = tid & 15;
    const int tmg = tid >> 4;
    const int n0  = tn * 8;
    const int m0  = tmg * 4;

    const unsigned sbase  = smem_u32(sm);
    const unsigned xbase  = sbase + XD_OFF + (unsigned)(m0 * 128) * 8;

    // ---- Phase 5: forward GEMM  y[m][n] = sum_k xu[m][k] * PiT[k][n] ----
    ull acc[16];
    #pragma unroll
    for (int i = 0; i < 16; i++) acc[i] = 0ULL;
    {
        unsigned xoff = xbase;
        unsigned poff = sbase + PIT_OFF + (unsigned)n0 * 4;
        #pragma unroll 8
        for (int k = 0; k < 128; k += 2) {
            ull x0[4], x1[4];
            #pragma unroll
            for (int mi = 0; mi < 4; mi++)
                lds_v2u64(x0[mi], x1[mi], xoff + mi * 1024);
            ull p[8];
            lds_v2u64(p[0], p[1], poff);
            lds_v2u64(p[2], p[3], poff + 16);
            lds_v2u64(p[4], p[5], poff + 528);
            lds_v2u64(p[6], p[7], poff + 544);
            #pragma unroll
            for (int mi = 0; mi < 4; mi++) {
                #pragma unroll
                for (int q = 0; q < 4; q++) {
                    fma2(acc[mi * 4 + q], x0[mi], p[q]);
                    fma2(acc[mi * 4 + q], x1[mi], p[4 + q]);
                }
            }
            xoff += 16;
            poff += 1056;
        }
    }

    // ---- Phase 6: scale by sqrt_d, quantize (argmin via strict midpoint counting) ----
    float mids[15];
    #pragma unroll
    for (int l = 0; l < 15; l++) mids[l] = s_mid[l];

    float aval[32];   // [mi][nj] quantized-reconstructed values (= codebook[idx]/sqrt_d)
    #pragma unroll
    for (int mi = 0; mi < 4; mi++) {
        #pragma unroll
        for (int q = 0; q < 4; q++) {
            float2 f = u2f(acc[mi * 4 + q]);
            float y0 = f.x * SQRTD_F;
            float y1 = f.y * SQRTD_F;
            int i0 = 0, i1 = 0;
            #pragma unroll
            for (int l = 0; l < 15; l++) {
                i0 += (y0 > mids[l]);
                i1 += (y1 > mids[l]);
            }
            aval[mi * 8 + 2 * q + 0] = s_csd[i0];
            aval[mi * 8 + 2 * q + 1] = s_csd[i1];
        }
    }

    __syncthreads();   // everyone done reading x_unit from Xd

    // ---- Phase 7: write quantized values (duplicated) back into Xd ----
    #pragma unroll
    for (int mi = 0; mi < 4; mi++) {
        float4* ad = (float4*)(sm + XD_OFF + (size_t)((m0 + mi) * 128 + n0) * 8);
        #pragma unroll
        for (int e = 0; e < 4; e++) {
            float a0 = aval[mi * 8 + 2 * e + 0];
            float a1 = aval[mi * 8 + 2 * e + 1];
            ad[e] = make_float4(a0, a0, a1, a1);
        }
    }
    __syncthreads();

    // ---- Phase 8: backward GEMM  z[m][i] = sum_j a[m][j] * Pi[j][i] ----
    #pragma unroll
    for (int i = 0; i < 16; i++) acc[i] = 0ULL;
    {
        unsigned xoff = xbase;
        unsigned poff = sbase + PIS_OFF + (unsigned)n0 * 4;
        #pragma unroll 8
        for (int k = 0; k < 128; k += 2) {
            ull x0[4], x1[4];
            #pragma unroll
            for (int mi = 0; mi < 4; mi++)
                lds_v2u64(x0[mi], x1[mi], xoff + mi * 1024);
            ull p[8];
            lds_v2u64(p[0], p[1], poff);
            lds_v2u64(p[2], p[3], poff + 16);
            lds_v2u64(p[4], p[5], poff + 528);
            lds_v2u64(p[6], p[7], poff + 544);
            #pragma unroll
            for (int mi = 0; mi < 4; mi++) {
                #pragma unroll
                for (int q = 0; q < 4; q++) {
                    fma2(acc[mi * 4 + q], x0[mi], p[q]);
                    fma2(acc[mi * 4 + q], x1[mi], p[4 + q]);
                }
            }
            xoff += 16;
            poff += 1056;
        }
    }

    // ---- Phase 9: scale by fp16-roundtripped norm, store ----
    #pragma unroll
    for (int mi = 0; mi < 4; mi++) {
        float nh = s_nh[m0 + mi];
        float2 f0 = u2f(acc[mi * 4 + 0]);
        float2 f1 = u2f(acc[mi * 4 + 1]);
        float2 f2 = u2f(acc[mi * 4 + 2]);
        float2 f3 = u2f(acc[mi * 4 + 3]);
        float4* orow = (float4*)(out + (size_t)(tok0 + m0 + mi) * 128 + n0);
        orow[0] = make_float4(f0.x * nh, f0.y * nh, f1.x * nh, f1.y * nh);
        orow[1] = make_float4(f2.x * nh, f2.y * nh, f3.x * nh, f3.y * nh);
    }
}

extern "C" void kernel_launch(void* const* d_in, const int* in_sizes, int n_in,
                              void* d_out, int out_size) {
    const float* x  = (const float*)d_in[0];
    const float* Pi = (const float*)d_in[1];
    const float* cb = (const float*)d_in[2];
    float* out = (float*)d_out;

    int ntok = in_sizes[0] / 128;
    int blocks = ntok / TOK_PER_BLK;

    static bool attr_set = false;
    // setting the attribute is idempotent and deterministic; do it every call
    cudaFuncSetAttribute(turboquant_kernel,
                         cudaFuncAttributeMaxDynamicSharedMemorySize, SMEM_BYTES);
    (void)attr_set;

    turboquant_kernel<<<blocks, NTHREADS, SMEM_BYTES>>>(x, Pi, cb, out, ntok);
}

// round 3
// speedup vs baseline: 1.9640x; 1.9640x over previous
#include <cuda_runtime.h>
#include <cuda_fp16.h>
#include <cstdint>

typedef uint32_t u32;

#define SQRTD_F 11.313708498984761f
#define PAD 132

// shared memory byte offsets
#define SM_PH   0                    // Pi hi  [128][132] f32
#define SM_PL   67584                // Pi lo
#define SM_A    135168               // A tile [128][132] f32
#define SM_MISC 202752
#define SMEM_BYTES 204992

static __device__ __forceinline__ float tf32_rna(float f) {
    u32 u;
    asm("cvt.rna.tf32.f32 %0, %1;" : "=r"(u) : "f"(f));
    return __uint_as_float(u);
}
static __device__ __forceinline__ u32 fb(float f) { return __float_as_uint(f); }

static __device__ __forceinline__ void mma8(float c[4], u32 a0, u32 a1, u32 a2, u32 a3,
                                            u32 b0, u32 b1) {
    asm volatile(
        "mma.sync.aligned.m16n8k8.row.col.f32.tf32.tf32.f32 "
        "{%0,%1,%2,%3},{%4,%5,%6,%7},{%8,%9},{%0,%1,%2,%3};"
        : "+f"(c[0]), "+f"(c[1]), "+f"(c[2]), "+f"(c[3])
        : "r"(a0), "r"(a1), "r"(a2), "r"(a3), "r"(b0), "r"(b1));
}

// One K=128 MMA chain over the full 128x(16-wide) warp tile.
// TR=false: B[k][n] = sB[n*PAD + k]   (fwd: B = PiT, stored as Pi rows)
// TR=true : B[k][n] = sB[k*PAD + n]   (bwd: B = Pi, transposed access)
template<bool TR>
static __device__ __forceinline__ void chain(const float* __restrict__ sA,
                                             const float* __restrict__ sB,
                                             float acc[8][2][4],
                                             int g, int t, int n0) {
    #pragma unroll 1
    for (int ks = 0; ks < 16; ks++) {
        const int k0 = ks * 8;
        u32 b[2][2];
        #pragma unroll
        for (int nt = 0; nt < 2; nt++) {
            const int n = n0 + nt * 8 + g;
            if (!TR) {
                b[nt][0] = fb(sB[n * PAD + k0 + t]);
                b[nt][1] = fb(sB[n * PAD + k0 + t + 4]);
            } else {
                b[nt][0] = fb(sB[(k0 + t) * PAD + n]);
                b[nt][1] = fb(sB[(k0 + t + 4) * PAD + n]);
            }
        }
        #pragma unroll
        for (int mt = 0; mt < 8; mt++) {
            const float* ar = sA + (mt * 16 + g) * PAD + k0 + t;
            u32 a0 = fb(ar[0]);
            u32 a1 = fb(ar[8 * PAD]);
            u32 a2 = fb(ar[4]);
            u32 a3 = fb(ar[8 * PAD + 4]);
            mma8(acc[mt][0], a0, a1, a2, a3, b[0][0], b[0][1]);
            mma8(acc[mt][1], a0, a1, a2, a3, b[1][0], b[1][1]);
        }
    }
}

__global__ __launch_bounds__(256, 1)
void tq_fused(const float* __restrict__ x, const float* __restrict__ Pi,
              const float* __restrict__ cbk, float* __restrict__ out) {
    extern __shared__ char sm[];
    float* sPH = (float*)(sm + SM_PH);
    float* sPL = (float*)(sm + SM_PL);
    float* sA  = (float*)(sm + SM_A);
    float* s_csdh = (float*)(sm + SM_MISC);
    float* s_csdl = (float*)(sm + SM_MISC + 64);
    float* s_mid  = (float*)(sm + SM_MISC + 128);
    float* s_part = (float*)(sm + SM_MISC + 192);
    float* s_cn   = (float*)(sm + SM_MISC + 1216);
    float* s_nh   = (float*)(sm + SM_MISC + 1728);

    const int tid = threadIdx.x;
    const int wid = tid >> 5, lane = tid & 31;
    const int g = lane >> 2, t = lane & 3;
    const int n0 = wid * 16;
    const int tok0 = blockIdx.x << 7;

    // ---- stage Pi hi/lo (row-major, padded) ----
    {
        const int prow = tid >> 1, pcol = (tid & 1) * 64;
        const float4* pr = (const float4*)(Pi + prow * 128 + pcol);
        #pragma unroll
        for (int e = 0; e < 16; e++) {
            float4 p = pr[e];
            float h0 = tf32_rna(p.x), h1 = tf32_rna(p.y);
            float h2 = tf32_rna(p.z), h3 = tf32_rna(p.w);
            *(float4*)(sPH + prow * PAD + pcol + 4 * e) = make_float4(h0, h1, h2, h3);
            *(float4*)(sPL + prow * PAD + pcol + 4 * e) =
                make_float4(tf32_rna(p.x - h0), tf32_rna(p.y - h1),
                            tf32_rna(p.z - h2), tf32_rna(p.w - h3));
        }
    }

    // ---- load x (2 threads/token), partial sum of squares ----
    const int token = tid >> 1, c0h = (tid & 1) * 64;
    const float4* xr = (const float4*)(x + (size_t)(tok0 + token) * 128 + c0h);
    {
        float ss = 0.f;
        float v[64];
        #pragma unroll
        for (int e = 0; e < 16; e++) {
            float4 p = xr[e];
            v[4 * e] = p.x; v[4 * e + 1] = p.y; v[4 * e + 2] = p.z; v[4 * e + 3] = p.w;
            ss += p.x * p.x + p.y * p.y + p.z * p.z + p.w * p.w;
        }
        s_part[tid] = ss;
        if (tid < 16) {
            float c = cbk[tid];
            float a = __fdiv_rn(c, SQRTD_F);
            float h = tf32_rna(a);
            s_csdh[tid] = h;
            s_csdl[tid] = tf32_rna(a - h);
            if (tid < 15) s_mid[tid] = (c + cbk[tid + 1]) * 0.5f;
        }
        __syncthreads();
        if (tid < 128) {
            float s = s_part[2 * tid] + s_part[2 * tid + 1];
            float n = __fsqrt_rn(s);
            s_cn[tid] = fmaxf(n, 1e-8f);
            s_nh[tid] = __half2float(__float2half_rn(n));
        }
        __syncthreads();
        // stage A_hi = tf32(x * sqrt_d / norm)
        const float scale = __fdiv_rn(SQRTD_F, s_cn[token]);
        #pragma unroll
        for (int e = 0; e < 16; e++) {
            *(float4*)(sA + token * PAD + c0h + 4 * e) = make_float4(
                tf32_rna(v[4 * e] * scale),     tf32_rna(v[4 * e + 1] * scale),
                tf32_rna(v[4 * e + 2] * scale), tf32_rna(v[4 * e + 3] * scale));
        }
    }
    __syncthreads();

    float acc[8][2][4];
    #pragma unroll
    for (int i = 0; i < 8; i++)
        #pragma unroll
        for (int j = 0; j < 2; j++)
            #pragma unroll
            for (int k = 0; k < 4; k++) acc[i][j][k] = 0.f;

    // ---- forward: A_hi*B_hi + A_hi*B_lo ----
    const float* Bs[2] = {sPH, sPL};
    #pragma unroll 1
    for (int c = 0; c < 2; c++) chain<false>(sA, Bs[c], acc, g, t, n0);
    __syncthreads();

    // ---- restage A_lo (reload x; compute lo) ----
    {
        const float scale = __fdiv_rn(SQRTD_F, s_cn[token]);
        #pragma unroll
        for (int e = 0; e < 16; e++) {
            float4 p = xr[e];
            float u0 = p.x * scale, u1 = p.y * scale, u2 = p.z * scale, u3 = p.w * scale;
            *(float4*)(sA + token * PAD + c0h + 4 * e) = make_float4(
                tf32_rna(u0 - tf32_rna(u0)), tf32_rna(u1 - tf32_rna(u1)),
                tf32_rna(u2 - tf32_rna(u2)), tf32_rna(u3 - tf32_rna(u3)));
        }
    }
    __syncthreads();
    chain<false>(sA, sPH, acc, g, t, n0);
    __syncthreads();

    // ---- quantize y -> idx (packed) ; stage Aq_hi ; reset acc ----
    u32 qidx[8];
    {
        float mids[15];
        #pragma unroll
        for (int l = 0; l < 15; l++) mids[l] = s_mid[l];
        #pragma unroll
        for (int mt = 0; mt < 8; mt++) {
            u32 pk = 0;
            #pragma unroll
            for (int nt = 0; nt < 2; nt++) {
                #pragma unroll
                for (int r = 0; r < 4; r++) {
                    float y = acc[mt][nt][r];
                    int idx = 0;
                    #pragma unroll
                    for (int l = 0; l < 15; l++) idx += (y > mids[l]);
                    pk |= (u32)idx << (4 * (nt * 4 + r));
                    int row = mt * 16 + g + (r >> 1) * 8;
                    int col = n0 + nt * 8 + 2 * t + (r & 1);
                    sA[row * PAD + col] = s_csdh[idx];
                    acc[mt][nt][r] = 0.f;
                }
            }
            qidx[mt] = pk;
        }
    }
    __syncthreads();

    // ---- backward: Aq_hi*Bt_hi + Aq_hi*Bt_lo ----
    #pragma unroll 1
    for (int c = 0; c < 2; c++) chain<true>(sA, Bs[c], acc, g, t, n0);
    __syncthreads();

    // ---- restage Aq_lo from packed indices ----
    #pragma unroll
    for (int mt = 0; mt < 8; mt++) {
        #pragma unroll
        for (int nt = 0; nt < 2; nt++) {
            #pragma unroll
            for (int r = 0; r < 4; r++) {
                int idx = (qidx[mt] >> (4 * (nt * 4 + r))) & 15;
                int row = mt * 16 + g + (r >> 1) * 8;
                int col = n0 + nt * 8 + 2 * t + (r & 1);
                sA[row * PAD + col] = s_csdl[idx];
            }
        }
    }
    __syncthreads();
    chain<true>(sA, sPH, acc, g, t, n0);

    // ---- epilogue: scale by fp16-roundtripped norm, store float2 ----
    #pragma unroll
    for (int mt = 0; mt < 8; mt++) {
        #pragma unroll
        for (int nt = 0; nt < 2; nt++) {
            int row0 = mt * 16 + g;
            int col  = n0 + nt * 8 + 2 * t;
            float nh0 = s_nh[row0];
            float nh1 = s_nh[row0 + 8];
            *(float2*)(out + (size_t)(tok0 + row0) * 128 + col) =
                make_float2(acc[mt][nt][0] * nh0, acc[mt][nt][1] * nh0);
            *(float2*)(out + (size_t)(tok0 + row0 + 8) * 128 + col) =
                make_float2(acc[mt][nt][2] * nh1, acc[mt][nt][3] * nh1);
        }
    }
}

extern "C" void kernel_launch(void* const* d_in, const int* in_sizes, int n_in,
                              void* d_out, int out_size) {
    const float* x   = (const float*)d_in[0];
    const float* Pi  = (const float*)d_in[1];
    const float* cbk = (const float*)d_in[2];
    float* out = (float*)d_out;

    int ntok = in_sizes[0] / 128;
    int blocks = ntok / 128;

    cudaFuncSetAttribute(tq_fused, cudaFuncAttributeMaxDynamicSharedMemorySize, SMEM_BYTES);
    tq_fused<<<blocks, 256, SMEM_BYTES>>>(x, Pi, cbk, out);
}